// round 8
// baseline (speedup 1.0000x reference)
#include <cuda_runtime.h>
#include <cuda_bf16.h>
#include <math.h>
#include <stdint.h>

#define NNODE 1000
#define NEDGE 16000
#define BATCH 32
#define TSTEP 64
#define CIN   8
#define HGC   16
#define HL    256
#define NOUTD 24
#define KDIM  8000          // N*C
#define JDIM  1024          // 4*HL
#define WIHK  16000         // N*HG
#define KP    24000         // extended K: A'=[Ah|Ah|Al], B'=[Bh|Bl|Bh]
#define MROWS 2048
#define BKT   64
#define NCHUNK (KP / BKT)   // 375

typedef unsigned long long u64;

// ---------------- scratch (device globals; no allocation) ----------------
__device__ __align__(16) __nv_bfloat16 g_Abf[MROWS * KP];   // 98.3 MB
__device__ __align__(16) __nv_bfloat16 g_Bbf[JDIM * KP];    // 49.2 MB
__device__ __align__(16) float g_x0agg[TSTEP * KDIM];       // 2 MB
__device__ __align__(16) float g_gates[TSTEP * BATCH * JDIM]; // 8.4 MB
__device__ __align__(16) float g_Wpk[HL * HL * 4];          // 1 MB: [k][u][gate]
__device__ float g_biasfull[JDIM];
__device__ float g_deginv[NNODE];
__device__ float g_norm[NEDGE];
__device__ int   g_colptr[NNODE + 1];
__device__ int   g_ecol[NEDGE];

// ---------------- helpers ----------------
__device__ __forceinline__ uint32_t smem_u32(const void* p) {
    uint32_t a;
    asm("{ .reg .u64 t; cvta.to.shared.u64 t, %1; cvt.u32.u64 %0, t; }" : "=r"(a) : "l"(p));
    return a;
}
#define CP_ASYNC16(saddr, gptr) \
    asm volatile("cp.async.cg.shared.global [%0], [%1], 16;" :: "r"(saddr), "l"(gptr))
#define CP_COMMIT() asm volatile("cp.async.commit_group;")
#define CP_WAIT(n)  asm volatile("cp.async.wait_group %0;" :: "n"(n))

#define LDMX4(r0, r1, r2, r3, a) \
    asm volatile("ldmatrix.sync.aligned.m8n8.x4.shared.b16 {%0,%1,%2,%3}, [%4];" \
        : "=r"(r0), "=r"(r1), "=r"(r2), "=r"(r3) : "r"(a))

#define MMA16816(c, a, b0, b1) \
    asm volatile("mma.sync.aligned.m16n8k16.row.col.f32.bf16.bf16.f32 " \
        "{%0,%1,%2,%3},{%4,%5,%6,%7},{%8,%9},{%0,%1,%2,%3};" \
        : "+f"((c)[0]), "+f"((c)[1]), "+f"((c)[2]), "+f"((c)[3]) \
        : "r"((a)[0]), "r"((a)[1]), "r"((a)[2]), "r"((a)[3]), "r"(b0), "r"(b1))

// ---------------- fused single-block graph prep ----------------
__global__ void __launch_bounds__(1024) k_prep(const int* __restrict__ ei,
                                               const float* __restrict__ ew,
                                               const float* __restrict__ bih,
                                               const float* __restrict__ bhh) {
    __shared__ float sdeg[NNODE];
    __shared__ float sdis[NNODE];
    __shared__ int   scnt[NNODE];
    __shared__ int   scur[NNODE];
    __shared__ int   sscan[1024];
    int tid = threadIdx.x;

    if (tid < NNODE) { sdeg[tid] = 1.0f; scnt[tid] = 0; }
    if (tid < JDIM) g_biasfull[tid] = bih[tid] + bhh[tid];
    __syncthreads();

    for (int e = tid; e < NEDGE; e += 1024)
        atomicAdd(&sdeg[ei[NEDGE + e]], ew[e]);
    __syncthreads();

    if (tid < NNODE) {
        float d = sdeg[tid];
        g_deginv[tid] = 1.0f / d;
        sdis[tid] = rsqrtf(d);
    }
    __syncthreads();

    for (int e = tid; e < NEDGE; e += 1024) {
        int r = ei[e], c = ei[NEDGE + e];
        g_norm[e] = sdis[r] * ew[e] * sdis[c];
        atomicAdd(&scnt[c], 1);
    }
    __syncthreads();

    int c = (tid < NNODE) ? scnt[tid] : 0;
    sscan[tid] = c;
    for (int off = 1; off < 1024; off <<= 1) {
        __syncthreads();
        int v = (tid >= off) ? sscan[tid - off] : 0;
        __syncthreads();
        sscan[tid] += v;
    }
    __syncthreads();
    if (tid < NNODE) {
        int ex = sscan[tid] - c;
        g_colptr[tid] = ex;
        scur[tid] = ex;
    }
    if (tid == NNODE - 1) g_colptr[NNODE] = sscan[tid];
    __syncthreads();

    for (int e = tid; e < NEDGE; e += 1024) {
        int pos = atomicAdd(&scur[ei[NEDGE + e]], 1);
        g_ecol[pos] = e;
    }
}

// ---------------- x0agg (R6 multi-block form) ----------------
__global__ void k_x0agg(const float* __restrict__ x, const int* __restrict__ ei) {
    int idx = blockIdx.x * blockDim.x + threadIdx.x;
    int c = idx & 7;
    int tm = idx >> 3;
    int m = tm % NNODE;
    int t = tm / NNODE;
    const float* xb = x + (size_t)t * KDIM;
    float acc = g_deginv[m] * xb[m * CIN + c];
    int s = g_colptr[m], epos = g_colptr[m + 1];
    for (int p = s; p < epos; p++) {
        int e = g_ecol[p];
        int r = ei[e];
        acc = fmaf(g_norm[e], xb[r * CIN + c], acc);
    }
    g_x0agg[(size_t)t * KDIM + m * CIN + c] = acc;
}

// ---------------- fused splitA + vraw + Whh pack ----------------
#define SPLITA_BLOCKS ((MROWS * 2000) / 256)   // 16000
#define VRAW_BLOCKS   ((JDIM * NNODE) / 256)   // 4000
#define PACK_BLOCKS   ((HL * HL) / 256)        // 256

__device__ __forceinline__ void do_splitA(const float* __restrict__ x, int blk) {
    int idx = blk * 256 + threadIdx.x;
    int r = idx / 2000, q = idx - r * 2000;
    const float* src = (r < 64) ? (g_x0agg + (size_t)r * KDIM) : (x + (size_t)r * KDIM);
    float4 v = *(const float4*)(src + q * 4);
    float vv[4] = {v.x, v.y, v.z, v.w};
    u64 hp, lp;
    __nv_bfloat16* hb = (__nv_bfloat16*)&hp;
    __nv_bfloat16* lb = (__nv_bfloat16*)&lp;
#pragma unroll
    for (int i = 0; i < 4; i++) {
        float f = vv[i];
        __nv_bfloat16 hi = __float2bfloat16(f);
        hb[i] = hi;
        lb[i] = __float2bfloat16(f - __bfloat162float(hi));
    }
    size_t base = (size_t)r * KP + q * 4;
    *(u64*)(g_Abf + base) = hp;
    *(u64*)(g_Abf + base + KDIM) = hp;
    *(u64*)(g_Abf + base + 2 * KDIM) = lp;
}

__device__ __forceinline__ void do_vraw(const float* __restrict__ Wih,
                                        const float* __restrict__ wg,
                                        const float* __restrict__ bgs, int blk) {
    int idx = blk * 256 + threadIdx.x;
    int j = idx / NNODE, n = idx % NNODE;
    float wih[HGC];
    const float4* p = (const float4*)(Wih + (size_t)j * WIHK + n * HGC);
#pragma unroll
    for (int q = 0; q < 4; q++) {
        float4 v = p[q];
        wih[q * 4 + 0] = v.x; wih[q * 4 + 1] = v.y; wih[q * 4 + 2] = v.z; wih[q * 4 + 3] = v.w;
    }
    uint4 hq, lq;
    __nv_bfloat16* hb = (__nv_bfloat16*)&hq;
    __nv_bfloat16* lb = (__nv_bfloat16*)&lq;
#pragma unroll
    for (int c = 0; c < CIN; c++) {
        float s = 0.f;
#pragma unroll
        for (int h = 0; h < HGC; h++) s = fmaf(wih[h], wg[c * HGC + h], s);
        __nv_bfloat16 hi = __float2bfloat16(s);
        hb[c] = hi;
        lb[c] = __float2bfloat16(s - __bfloat162float(hi));
    }
    size_t base = (size_t)j * KP + n * CIN;
    *(uint4*)(g_Bbf + base) = hq;
    *(uint4*)(g_Bbf + base + KDIM) = lq;
    *(uint4*)(g_Bbf + base + 2 * KDIM) = hq;
    float bpart = 0.f;
#pragma unroll
    for (int h = 0; h < HGC; h++) bpart = fmaf(wih[h], bgs[h], bpart);
    atomicAdd(&g_biasfull[j], bpart);
}

// Wpk[(k*256+u)*4 + g] = Whh[g*256+u][k]
__device__ __forceinline__ void do_pack(const float* __restrict__ Whh, int blk) {
    int idx = blk * 256 + threadIdx.x;   // 0..65535
    int k = idx >> 8, u = idx & 255;
    float4 w;
    w.x = Whh[(size_t)(0 * HL + u) * HL + k];
    w.y = Whh[(size_t)(1 * HL + u) * HL + k];
    w.z = Whh[(size_t)(2 * HL + u) * HL + k];
    w.w = Whh[(size_t)(3 * HL + u) * HL + k];
    *(float4*)(g_Wpk + (size_t)idx * 4) = w;
}

__global__ void __launch_bounds__(256) k_fused(const float* __restrict__ x,
                                               const float* __restrict__ Wih,
                                               const float* __restrict__ Wg,
                                               const float* __restrict__ bg,
                                               const float* __restrict__ Whh) {
    __shared__ float wg[CIN * HGC];
    __shared__ float bgs[HGC];
    int blk = blockIdx.x;
    if (blk < SPLITA_BLOCKS) {
        do_splitA(x, blk);
    } else if (blk < SPLITA_BLOCKS + VRAW_BLOCKS) {
        if (threadIdx.x < CIN * HGC) wg[threadIdx.x] = Wg[threadIdx.x];
        if (threadIdx.x < HGC) bgs[threadIdx.x] = bg[threadIdx.x];
        __syncthreads();
        do_vraw(Wih, wg, bgs, blk - SPLITA_BLOCKS);
    } else {
        do_pack(Whh, blk - SPLITA_BLOCKS - VRAW_BLOCKS);
    }
}

// ---------------- HMMA GEMM: 128x128 tile, K'=24000, 3-stage cp.async ----------------
#define SOFF_BIAS 0
#define SOFF_A 1024
#define SOFF_B (1024 + 3 * 16384)
#define GEMM_SMEM (1024 + 6 * 16384)

__global__ void __launch_bounds__(256) k_mma() {
    extern __shared__ __align__(1024) char smem[];
    const int tid = threadIdx.x, wid = tid >> 5, lane = tid & 31;
    const int bm = blockIdx.x, bn = blockIdx.y;
    uint32_t sb = smem_u32(smem);

    float* sbias = (float*)(smem + SOFF_BIAS);
    if (tid < 128) sbias[tid] = g_biasfull[bn * 128 + tid];

    const __nv_bfloat16* Ab = g_Abf + (size_t)bm * 128 * KP;
    const __nv_bfloat16* Bb = g_Bbf + (size_t)bn * 128 * KP;

    int ld_r[4], ld_sw[4], ld_c[4];
#pragma unroll
    for (int it = 0; it < 4; it++) {
        int idx = tid + it * 256;
        int r = idx >> 3, c16 = idx & 7;
        ld_r[it] = r;
        ld_c[it] = c16;
        ld_sw[it] = r * 128 + ((c16 * 16) ^ ((r & 7) << 4));
    }

#define LOAD_STAGE(stage, kb)                                                     \
    do {                                                                          \
        uint32_t _sA = sb + SOFF_A + (stage) * 16384;                             \
        uint32_t _sB = sb + SOFF_B + (stage) * 16384;                             \
        _Pragma("unroll")                                                         \
        for (int _it = 0; _it < 4; _it++) {                                       \
            CP_ASYNC16(_sA + ld_sw[_it],                                          \
                       Ab + (size_t)ld_r[_it] * KP + (kb) + ld_c[_it] * 8);       \
            CP_ASYNC16(_sB + ld_sw[_it],                                          \
                       Bb + (size_t)ld_r[_it] * KP + (kb) + ld_c[_it] * 8);       \
        }                                                                         \
        CP_COMMIT();                                                              \
    } while (0)

    const int wm = wid & 1, wn = wid >> 1;
    const int a_rl = lane & 15, a_ck = lane >> 4;
    const int b_nl = (lane & 7) + ((lane >> 4) << 3), b_ck = (lane >> 3) & 1;

    float acc[4][4][4];
#pragma unroll
    for (int i = 0; i < 4; i++)
#pragma unroll
        for (int j = 0; j < 4; j++)
#pragma unroll
            for (int q = 0; q < 4; q++) acc[i][j][q] = 0.f;

    LOAD_STAGE(0, 0);
    LOAD_STAGE(1, BKT);

    for (int c = 0; c < NCHUNK; c++) {
        int s = c % 3;
        if (c + 2 < NCHUNK) LOAD_STAGE((c + 2) % 3, (c + 2) * BKT);
        CP_WAIT(2);
        __syncthreads();

        uint32_t aBase = sb + SOFF_A + s * 16384;
        uint32_t bBase = sb + SOFF_B + s * 16384;
#pragma unroll
        for (int ks = 0; ks < 4; ks++) {
            uint32_t af[4][4];
#pragma unroll
            for (int fm = 0; fm < 4; fm++) {
                int r = wm * 64 + fm * 16 + a_rl;
                uint32_t addr = aBase + r * 128 + ((((ks * 2 + a_ck) * 16)) ^ ((r & 7) << 4));
                LDMX4(af[fm][0], af[fm][1], af[fm][2], af[fm][3], addr);
            }
            uint32_t bf[2][4];
#pragma unroll
            for (int bi = 0; bi < 2; bi++) {
                int n = wn * 32 + bi * 16 + b_nl;
                uint32_t addr = bBase + n * 128 + ((((ks * 2 + b_ck) * 16)) ^ ((n & 7) << 4));
                LDMX4(bf[bi][0], bf[bi][1], bf[bi][2], bf[bi][3], addr);
            }
#pragma unroll
            for (int fm = 0; fm < 4; fm++)
#pragma unroll
                for (int fn = 0; fn < 4; fn++) {
                    uint32_t b0 = bf[fn >> 1][(fn & 1) * 2];
                    uint32_t b1 = bf[fn >> 1][(fn & 1) * 2 + 1];
                    MMA16816(acc[fm][fn], af[fm], b0, b1);
                }
        }
        __syncthreads();
    }

    const int gid = lane >> 2, tg = lane & 3;
#pragma unroll
    for (int fm = 0; fm < 4; fm++) {
        int m0 = bm * 128 + wm * 64 + fm * 16 + gid;
        int b0i = m0 >> 6, t0 = m0 & 63;
        int m1 = m0 + 8;
        int b1i = m1 >> 6, t1 = m1 & 63;
        float* g0 = g_gates + (size_t)t0 * (BATCH * JDIM) + b0i * JDIM + bn * 128;
        float* g1 = g_gates + (size_t)t1 * (BATCH * JDIM) + b1i * JDIM + bn * 128;
#pragma unroll
        for (int fn = 0; fn < 4; fn++) {
            int jl = wn * 32 + fn * 8 + tg * 2;
            float bx = sbias[jl], by = sbias[jl + 1];
            float2 v0 = make_float2(acc[fm][fn][0] + bx, acc[fm][fn][1] + by);
            float2 v1 = make_float2(acc[fm][fn][2] + bx, acc[fm][fn][3] + by);
            *(float2*)(g0 + jl) = v0;
            *(float2*)(g1 + jl) = v1;
        }
    }
#undef LOAD_STAGE
}

// ---------------- batch-parallel LSTM (no grid barrier) + fused projection ----------------
__device__ __forceinline__ float sigf(float x) { return 1.0f / (1.0f + expf(-x)); }

__global__ void __launch_bounds__(256) k_lstm(const float* __restrict__ Wp,
                                              const float* __restrict__ bp,
                                              float* __restrict__ out) {
    __shared__ float hsm[HL];
    const int b = blockIdx.x, u = threadIdx.x;
    hsm[u] = 0.f;
    float creg = 0.f;
    __syncthreads();

    const float4* Wp4 = (const float4*)g_Wpk;   // [k*256+u] -> gates i,f,g,o

    for (int t = 0; t < TSTEP; t++) {
        float ai = 0.f, af = 0.f, ag = 0.f, ao = 0.f;
#pragma unroll 8
        for (int k = 0; k < HL; k++) {
            float hk = hsm[k];
            float4 w = Wp4[k * HL + u];
            ai = fmaf(w.x, hk, ai);
            af = fmaf(w.y, hk, af);
            ag = fmaf(w.z, hk, ag);
            ao = fmaf(w.w, hk, ao);
        }
        const float* gin = g_gates + (size_t)t * (BATCH * JDIM) + b * JDIM;
        float gi = __ldg(gin + u) + ai;
        float gf = __ldg(gin + HL + u) + af;
        float gg = __ldg(gin + 2 * HL + u) + ag;
        float go = __ldg(gin + 3 * HL + u) + ao;
        float cn = sigf(gf) * creg + sigf(gi) * tanhf(gg);
        float hn = sigf(go) * tanhf(cn);
        creg = cn;
        __syncthreads();
        hsm[u] = hn;
        __syncthreads();
    }

    // fused projection: out[b,o] = dot(hsm, Wp[o,:]) + bp[o]
    int warp = u >> 5, lane = u & 31;
    for (int o = warp; o < NOUTD; o += 8) {
        const float* w = Wp + (size_t)o * HL;
        float s = 0.f;
#pragma unroll
        for (int q = 0; q < 8; q++) {
            int k = lane + q * 32;
            s = fmaf(hsm[k], __ldg(w + k), s);
        }
#pragma unroll
        for (int off = 16; off > 0; off >>= 1)
            s += __shfl_down_sync(0xFFFFFFFF, s, off);
        if (lane == 0) out[b * NOUTD + o] = s + bp[o];
    }
}

// ---------------- launch ----------------
extern "C" void kernel_launch(void* const* d_in, const int* in_sizes, int n_in,
                              void* d_out, int out_size) {
    const float* x   = (const float*)d_in[0];
    const int*   ei  = (const int*)d_in[1];
    const float* ew  = (const float*)d_in[2];
    const float* Wg  = (const float*)d_in[3];
    const float* bg  = (const float*)d_in[4];
    const float* Wih = (const float*)d_in[5];
    const float* Whh = (const float*)d_in[6];
    const float* bih = (const float*)d_in[7];
    const float* bhh = (const float*)d_in[8];
    const float* Wp  = (const float*)d_in[9];
    const float* bp  = (const float*)d_in[10];
    float* out = (float*)d_out;

    (void)in_sizes; (void)n_in; (void)out_size;

    cudaFuncSetAttribute(k_mma, cudaFuncAttributeMaxDynamicSharedMemorySize, GEMM_SMEM);

    k_prep<<<1, 1024>>>(ei, ew, bih, bhh);
    k_x0agg<<<(TSTEP * NNODE * CIN + 255) / 256, 256>>>(x, ei);
    k_fused<<<SPLITA_BLOCKS + VRAW_BLOCKS + PACK_BLOCKS, 256>>>(x, Wih, Wg, bg, Whh);
    k_mma<<<dim3(16, 8), 256, GEMM_SMEM>>>();
    k_lstm<<<BATCH, 256>>>(Wp, bp, out);
}

// round 9
// speedup vs baseline: 2.3054x; 2.3054x over previous
#include <cuda_runtime.h>
#include <cuda_bf16.h>
#include <math.h>
#include <stdint.h>

#define NNODE 1000
#define NEDGE 16000
#define BATCH 32
#define TSTEP 64
#define CIN   8
#define HGC   16
#define HL    256
#define NOUTD 24
#define KDIM  8000          // N*C
#define JDIM  1024          // 4*HL
#define WIHK  16000         // N*HG
#define KP    24000         // extended K: A'=[Ah|Ah|Al], B'=[Bh|Bl|Bh]
#define MROWS 2048
#define BKT   64
#define NCHUNK (KP / BKT)   // 375

typedef unsigned long long u64;

// ---------------- scratch (device globals; no allocation) ----------------
__device__ __align__(16) __nv_bfloat16 g_Abf[MROWS * KP];   // 98.3 MB
__device__ __align__(16) __nv_bfloat16 g_Bbf[JDIM * KP];    // 49.2 MB
__device__ __align__(16) float g_x0agg[TSTEP * KDIM];       // 2 MB
__device__ __align__(16) float g_gates[TSTEP * BATCH * JDIM]; // 8.4 MB
__device__ float g_biasfull[JDIM];
__device__ float g_deginv[NNODE];
__device__ float g_norm[NEDGE];
__device__ int   g_colptr[NNODE + 1];
__device__ int   g_ecol[NEDGE];
__device__ __align__(16) float g_hst[2][BATCH * HL];
__device__ int   g_bcnt;

// ---------------- helpers ----------------
__device__ __forceinline__ uint32_t smem_u32(const void* p) {
    uint32_t a;
    asm("{ .reg .u64 t; cvta.to.shared.u64 t, %1; cvt.u32.u64 %0, t; }" : "=r"(a) : "l"(p));
    return a;
}
#define CP_ASYNC16(saddr, gptr) \
    asm volatile("cp.async.cg.shared.global [%0], [%1], 16;" :: "r"(saddr), "l"(gptr))
#define CP_COMMIT() asm volatile("cp.async.commit_group;")
#define CP_WAIT(n)  asm volatile("cp.async.wait_group %0;" :: "n"(n))

#define LDMX4(r0, r1, r2, r3, a) \
    asm volatile("ldmatrix.sync.aligned.m8n8.x4.shared.b16 {%0,%1,%2,%3}, [%4];" \
        : "=r"(r0), "=r"(r1), "=r"(r2), "=r"(r3) : "r"(a))

#define MMA16816(c, a, b0, b1) \
    asm volatile("mma.sync.aligned.m16n8k16.row.col.f32.bf16.bf16.f32 " \
        "{%0,%1,%2,%3},{%4,%5,%6,%7},{%8,%9},{%0,%1,%2,%3};" \
        : "+f"((c)[0]), "+f"((c)[1]), "+f"((c)[2]), "+f"((c)[3]) \
        : "r"((a)[0]), "r"((a)[1]), "r"((a)[2]), "r"((a)[3]), "r"(b0), "r"(b1))

// ---------------- f32x2 (LSTM) ----------------
__device__ __forceinline__ u64 pack2(float lo, float hi) {
    u64 r; asm("mov.b64 %0, {%1, %2};" : "=l"(r) : "f"(lo), "f"(hi)); return r;
}
__device__ __forceinline__ void unpack2(float& lo, float& hi, u64 v) {
    asm("mov.b64 {%0, %1}, %2;" : "=f"(lo), "=f"(hi) : "l"(v));
}
#define FFMA2(acc, a, w) asm("fma.rn.f32x2 %0, %1, %2, %0;" : "+l"(acc) : "l"(a), "l"(w))

// ---------------- fused single-block graph prep ----------------
__global__ void __launch_bounds__(1024) k_prep(const int* __restrict__ ei,
                                               const float* __restrict__ ew,
                                               const float* __restrict__ bih,
                                               const float* __restrict__ bhh) {
    __shared__ float sdeg[NNODE];
    __shared__ float sdis[NNODE];
    __shared__ int   scnt[NNODE];
    __shared__ int   scur[NNODE];
    __shared__ int   sscan[1024];
    int tid = threadIdx.x;

    if (tid < NNODE) { sdeg[tid] = 1.0f; scnt[tid] = 0; }
    if (tid < JDIM) g_biasfull[tid] = bih[tid] + bhh[tid];
    for (int i = tid; i < BATCH * HL; i += 1024) g_hst[0][i] = 0.f;
    if (tid == 0) g_bcnt = 0;
    __syncthreads();

    for (int e = tid; e < NEDGE; e += 1024)
        atomicAdd(&sdeg[ei[NEDGE + e]], ew[e]);
    __syncthreads();

    if (tid < NNODE) {
        float d = sdeg[tid];
        g_deginv[tid] = 1.0f / d;
        sdis[tid] = rsqrtf(d);
    }
    __syncthreads();

    for (int e = tid; e < NEDGE; e += 1024) {
        int r = ei[e], c = ei[NEDGE + e];
        g_norm[e] = sdis[r] * ew[e] * sdis[c];
        atomicAdd(&scnt[c], 1);
    }
    __syncthreads();

    int c = (tid < NNODE) ? scnt[tid] : 0;
    sscan[tid] = c;
    for (int off = 1; off < 1024; off <<= 1) {
        __syncthreads();
        int v = (tid >= off) ? sscan[tid - off] : 0;
        __syncthreads();
        sscan[tid] += v;
    }
    __syncthreads();
    if (tid < NNODE) {
        int ex = sscan[tid] - c;
        g_colptr[tid] = ex;
        scur[tid] = ex;
    }
    if (tid == NNODE - 1) g_colptr[NNODE] = sscan[tid];
    __syncthreads();

    for (int e = tid; e < NEDGE; e += 1024) {
        int pos = atomicAdd(&scur[ei[NEDGE + e]], 1);
        g_ecol[pos] = e;
    }
}

// ---------------- x0agg (multi-block, R6 form) ----------------
__global__ void k_x0agg(const float* __restrict__ x, const int* __restrict__ ei) {
    int idx = blockIdx.x * blockDim.x + threadIdx.x;
    int c = idx & 7;
    int tm = idx >> 3;
    int m = tm % NNODE;
    int t = tm / NNODE;
    const float* xb = x + (size_t)t * KDIM;
    float acc = g_deginv[m] * xb[m * CIN + c];
    int s = g_colptr[m], epos = g_colptr[m + 1];
    for (int p = s; p < epos; p++) {
        int e = g_ecol[p];
        int r = ei[e];
        acc = fmaf(g_norm[e], xb[r * CIN + c], acc);
    }
    g_x0agg[(size_t)t * KDIM + m * CIN + c] = acc;
}

// ---------------- fused splitA + vraw ----------------
#define SPLITA_BLOCKS ((MROWS * 2000) / 256)   // 16000
#define VRAW_BLOCKS   ((JDIM * NNODE) / 256)   // 4000

__device__ __forceinline__ void do_splitA(const float* __restrict__ x, int blk) {
    int idx = blk * 256 + threadIdx.x;
    int r = idx / 2000, q = idx - r * 2000;
    const float* src = (r < 64) ? (g_x0agg + (size_t)r * KDIM) : (x + (size_t)r * KDIM);
    float4 v = *(const float4*)(src + q * 4);
    float vv[4] = {v.x, v.y, v.z, v.w};
    u64 hp, lp;
    __nv_bfloat16* hb = (__nv_bfloat16*)&hp;
    __nv_bfloat16* lb = (__nv_bfloat16*)&lp;
#pragma unroll
    for (int i = 0; i < 4; i++) {
        float f = vv[i];
        __nv_bfloat16 hi = __float2bfloat16(f);
        hb[i] = hi;
        lb[i] = __float2bfloat16(f - __bfloat162float(hi));
    }
    size_t base = (size_t)r * KP + q * 4;
    *(u64*)(g_Abf + base) = hp;
    *(u64*)(g_Abf + base + KDIM) = hp;
    *(u64*)(g_Abf + base + 2 * KDIM) = lp;
}

__device__ __forceinline__ void do_vraw(const float* __restrict__ Wih,
                                        const float* __restrict__ wg,
                                        const float* __restrict__ bgs, int blk) {
    int idx = blk * 256 + threadIdx.x;
    int j = idx / NNODE, n = idx % NNODE;
    float wih[HGC];
    const float4* p = (const float4*)(Wih + (size_t)j * WIHK + n * HGC);
#pragma unroll
    for (int q = 0; q < 4; q++) {
        float4 v = p[q];
        wih[q * 4 + 0] = v.x; wih[q * 4 + 1] = v.y; wih[q * 4 + 2] = v.z; wih[q * 4 + 3] = v.w;
    }
    uint4 hq, lq;
    __nv_bfloat16* hb = (__nv_bfloat16*)&hq;
    __nv_bfloat16* lb = (__nv_bfloat16*)&lq;
#pragma unroll
    for (int c = 0; c < CIN; c++) {
        float s = 0.f;
#pragma unroll
        for (int h = 0; h < HGC; h++) s = fmaf(wih[h], wg[c * HGC + h], s);
        __nv_bfloat16 hi = __float2bfloat16(s);
        hb[c] = hi;
        lb[c] = __float2bfloat16(s - __bfloat162float(hi));
    }
    size_t base = (size_t)j * KP + n * CIN;
    *(uint4*)(g_Bbf + base) = hq;
    *(uint4*)(g_Bbf + base + KDIM) = lq;
    *(uint4*)(g_Bbf + base + 2 * KDIM) = hq;
    float bpart = 0.f;
#pragma unroll
    for (int h = 0; h < HGC; h++) bpart = fmaf(wih[h], bgs[h], bpart);
    atomicAdd(&g_biasfull[j], bpart);
}

__global__ void __launch_bounds__(256) k_fused(const float* __restrict__ x,
                                               const float* __restrict__ Wih,
                                               const float* __restrict__ Wg,
                                               const float* __restrict__ bg) {
    __shared__ float wg[CIN * HGC];
    __shared__ float bgs[HGC];
    int blk = blockIdx.x;
    if (blk < SPLITA_BLOCKS) {
        do_splitA(x, blk);
    } else {
        if (threadIdx.x < CIN * HGC) wg[threadIdx.x] = Wg[threadIdx.x];
        if (threadIdx.x < HGC) bgs[threadIdx.x] = bg[threadIdx.x];
        __syncthreads();
        do_vraw(Wih, wg, bgs, blk - SPLITA_BLOCKS);
    }
}

// ---------------- HMMA GEMM: 128x128 tile, K'=24000, 3-stage cp.async ----------------
#define SOFF_BIAS 0
#define SOFF_A 1024
#define SOFF_B (1024 + 3 * 16384)
#define GEMM_SMEM (1024 + 6 * 16384)

__global__ void __launch_bounds__(256) k_mma() {
    extern __shared__ __align__(1024) char smem[];
    const int tid = threadIdx.x, wid = tid >> 5, lane = tid & 31;
    const int bm = blockIdx.x, bn = blockIdx.y;
    uint32_t sb = smem_u32(smem);

    float* sbias = (float*)(smem + SOFF_BIAS);
    if (tid < 128) sbias[tid] = g_biasfull[bn * 128 + tid];

    const __nv_bfloat16* Ab = g_Abf + (size_t)bm * 128 * KP;
    const __nv_bfloat16* Bb = g_Bbf + (size_t)bn * 128 * KP;

    int ld_r[4], ld_sw[4], ld_c[4];
#pragma unroll
    for (int it = 0; it < 4; it++) {
        int idx = tid + it * 256;
        int r = idx >> 3, c16 = idx & 7;
        ld_r[it] = r;
        ld_c[it] = c16;
        ld_sw[it] = r * 128 + ((c16 * 16) ^ ((r & 7) << 4));
    }

#define LOAD_STAGE(stage, kb)                                                     \
    do {                                                                          \
        uint32_t _sA = sb + SOFF_A + (stage) * 16384;                             \
        uint32_t _sB = sb + SOFF_B + (stage) * 16384;                             \
        _Pragma("unroll")                                                         \
        for (int _it = 0; _it < 4; _it++) {                                       \
            CP_ASYNC16(_sA + ld_sw[_it],                                          \
                       Ab + (size_t)ld_r[_it] * KP + (kb) + ld_c[_it] * 8);       \
            CP_ASYNC16(_sB + ld_sw[_it],                                          \
                       Bb + (size_t)ld_r[_it] * KP + (kb) + ld_c[_it] * 8);       \
        }                                                                         \
        CP_COMMIT();                                                              \
    } while (0)

    const int wm = wid & 1, wn = wid >> 1;
    const int a_rl = lane & 15, a_ck = lane >> 4;
    const int b_nl = (lane & 7) + ((lane >> 4) << 3), b_ck = (lane >> 3) & 1;

    float acc[4][4][4];
#pragma unroll
    for (int i = 0; i < 4; i++)
#pragma unroll
        for (int j = 0; j < 4; j++)
#pragma unroll
            for (int q = 0; q < 4; q++) acc[i][j][q] = 0.f;

    LOAD_STAGE(0, 0);
    LOAD_STAGE(1, BKT);

    for (int c = 0; c < NCHUNK; c++) {
        int s = c % 3;
        if (c + 2 < NCHUNK) LOAD_STAGE((c + 2) % 3, (c + 2) * BKT);
        CP_WAIT(2);
        __syncthreads();

        uint32_t aBase = sb + SOFF_A + s * 16384;
        uint32_t bBase = sb + SOFF_B + s * 16384;
#pragma unroll
        for (int ks = 0; ks < 4; ks++) {
            uint32_t af[4][4];
#pragma unroll
            for (int fm = 0; fm < 4; fm++) {
                int r = wm * 64 + fm * 16 + a_rl;
                uint32_t addr = aBase + r * 128 + ((((ks * 2 + a_ck) * 16)) ^ ((r & 7) << 4));
                LDMX4(af[fm][0], af[fm][1], af[fm][2], af[fm][3], addr);
            }
            uint32_t bf[2][4];
#pragma unroll
            for (int bi = 0; bi < 2; bi++) {
                int n = wn * 32 + bi * 16 + b_nl;
                uint32_t addr = bBase + n * 128 + ((((ks * 2 + b_ck) * 16)) ^ ((n & 7) << 4));
                LDMX4(bf[bi][0], bf[bi][1], bf[bi][2], bf[bi][3], addr);
            }
#pragma unroll
            for (int fm = 0; fm < 4; fm++)
#pragma unroll
                for (int fn = 0; fn < 4; fn++) {
                    uint32_t b0 = bf[fn >> 1][(fn & 1) * 2];
                    uint32_t b1 = bf[fn >> 1][(fn & 1) * 2 + 1];
                    MMA16816(acc[fm][fn], af[fm], b0, b1);
                }
        }
        __syncthreads();
    }

    const int gid = lane >> 2, tg = lane & 3;
#pragma unroll
    for (int fm = 0; fm < 4; fm++) {
        int m0 = bm * 128 + wm * 64 + fm * 16 + gid;
        int b0i = m0 >> 6, t0 = m0 & 63;
        int m1 = m0 + 8;
        int b1i = m1 >> 6, t1 = m1 & 63;
        float* g0 = g_gates + (size_t)t0 * (BATCH * JDIM) + b0i * JDIM + bn * 128;
        float* g1 = g_gates + (size_t)t1 * (BATCH * JDIM) + b1i * JDIM + bn * 128;
#pragma unroll
        for (int fn = 0; fn < 4; fn++) {
            int jl = wn * 32 + fn * 8 + tg * 2;
            float bx = sbias[jl], by = sbias[jl + 1];
            float2 v0 = make_float2(acc[fm][fn][0] + bx, acc[fm][fn][1] + by);
            float2 v1 = make_float2(acc[fm][fn][2] + bx, acc[fm][fn][3] + by);
            *(float2*)(g0 + jl) = v0;
            *(float2*)(g1 + jl) = v1;
        }
    }
#undef LOAD_STAGE
}

// ---------------- persistent LSTM, release/acquire generation barrier ----------------
__device__ __forceinline__ float sigf(float x) { return 1.0f / (1.0f + expf(-x)); }

#define LBLK 64   // blocks; each owns 4 units
__global__ void __launch_bounds__(128) k_lstm(const float* __restrict__ Whh) {
    __shared__ __align__(16) float Wsm[16][HL];       // 16 KB (rows: jj*4+g)
    __shared__ u64 hp[HL / 2][33];                    // packed h, padded
    int tid = threadIdx.x;
    int u0 = blockIdx.x * 4;
    for (int i = tid; i < 16 * HL; i += 128) {
        int r = i >> 8, k = i & 255;
        int jj = r >> 2, g = r & 3;
        Wsm[r][k] = Whh[(size_t)(g * HL + u0 + jj) * HL + k];
    }
    int b = tid & 31, jj = tid >> 5;   // warp == jj
    int u = u0 + jj;
    float creg = 0.f;

    for (int t = 0; t < TSTEP; t++) {
        int p = t & 1;
        __syncthreads();
        // load h (L1-bypass: .cg) into packed smem
        const float* hsrc = g_hst[p];
        for (int i = tid; i < BATCH * (HL / 2); i += 128) {
            int k2 = i & 127, bb = i >> 7;
            float hx, hy;
            asm volatile("ld.global.cg.v2.f32 {%0, %1}, [%2];"
                         : "=f"(hx), "=f"(hy) : "l"(hsrc + bb * HL + k2 * 2));
            hp[k2][bb] = pack2(hx, hy);
        }
        __syncthreads();
        u64 acc[4] = {0ull, 0ull, 0ull, 0ull};
#pragma unroll 4
        for (int k2 = 0; k2 < HL / 2; k2++) {
            u64 h2 = hp[k2][b];
#pragma unroll
            for (int g = 0; g < 4; g++) {
                u64 w2 = *(const u64*)&Wsm[jj * 4 + g][k2 * 2];
                FFMA2(acc[g], h2, w2);
            }
        }
        const float* gin = g_gates + (size_t)t * (BATCH * JDIM) + b * JDIM;
        float gv[4];
#pragma unroll
        for (int g = 0; g < 4; g++) {
            float lo, hi; unpack2(lo, hi, acc[g]);
            gv[g] = lo + hi + __ldg(gin + g * HL + u);
        }
        float cn = sigf(gv[1]) * creg + sigf(gv[0]) * tanhf(gv[2]);
        float hn = sigf(gv[3]) * tanhf(cn);
        creg = cn;
        // store h (L1-bypass)
        asm volatile("st.global.cg.f32 [%0], %1;"
                     :: "l"(g_hst[1 - p] + b * HL + u), "f"(hn));
        __syncthreads();   // all stores of this block issued
        if (tid == 0) {
            int old;
            asm volatile("atom.global.add.release.gpu.s32 %0, [%1], %2;"
                         : "=r"(old) : "l"(&g_bcnt), "r"(1) : "memory");
            int target = (t + 1) * LBLK;
            int v = old + 1;
            while (v < target) {
                asm volatile("ld.global.acquire.gpu.s32 %0, [%1];"
                             : "=r"(v) : "l"(&g_bcnt) : "memory");
            }
        }
        __syncthreads();
    }
}

// out[b,o] = h_last[b,:].W_proj[o,:] + b_proj[o]   (h_last = g_hst[0] after 64 steps)
__global__ void k_proj(const float* __restrict__ Wp, const float* __restrict__ bp,
                       float* __restrict__ out) {
    int tid = threadIdx.x;
    if (tid >= BATCH * NOUTD) return;
    int b = tid / NOUTD, o = tid % NOUTD;
    const float* h = g_hst[0] + b * HL;
    const float* w = Wp + o * HL;
    float s = 0.f;
#pragma unroll 8
    for (int k = 0; k < HL; k++) s = fmaf(h[k], w[k], s);
    out[b * NOUTD + o] = s + bp[o];
}

// ---------------- launch ----------------
extern "C" void kernel_launch(void* const* d_in, const int* in_sizes, int n_in,
                              void* d_out, int out_size) {
    const float* x   = (const float*)d_in[0];
    const int*   ei  = (const int*)d_in[1];
    const float* ew  = (const float*)d_in[2];
    const float* Wg  = (const float*)d_in[3];
    const float* bg  = (const float*)d_in[4];
    const float* Wih = (const float*)d_in[5];
    const float* Whh = (const float*)d_in[6];
    const float* bih = (const float*)d_in[7];
    const float* bhh = (const float*)d_in[8];
    const float* Wp  = (const float*)d_in[9];
    const float* bp  = (const float*)d_in[10];
    float* out = (float*)d_out;

    (void)in_sizes; (void)n_in; (void)out_size;

    cudaFuncSetAttribute(k_mma, cudaFuncAttributeMaxDynamicSharedMemorySize, GEMM_SMEM);

    k_prep<<<1, 1024>>>(ei, ew, bih, bhh);
    k_x0agg<<<(TSTEP * NNODE * CIN + 255) / 256, 256>>>(x, ei);
    k_fused<<<SPLITA_BLOCKS + VRAW_BLOCKS, 256>>>(x, Wih, Wg, bg);
    k_mma<<<dim3(16, 8), 256, GEMM_SMEM>>>();
    k_lstm<<<LBLK, 128>>>(Whh);
    k_proj<<<1, BATCH * NOUTD>>>(Wp, bp, out);
}